// round 11
// baseline (speedup 1.0000x reference)
#include <cuda_runtime.h>
#include <cuda_fp16.h>
#include <cstdint>

#define NNODES 50000
#define NEDGES 800000
#define H 128
#define FE 16
#define TILE_M 64
#define THREADS_E 128
#define THREADS 256
#define TILE_N 32
#define NCHUNKS 5
#define NCHUNK1 1

// fp16 strides (halves)
#define PQS16  136     // PQ stage / mid row stride: 68 words, 68%32=4 -> conflict-free
#define MIDS16 136     // nodeP tile stride
#define SF16   40
#define WS16   40

#define SF_HALVES   (TILE_M * SF16)                 // 2560
#define PQ_HALVES   (128 * PQS16)                   // 17408 (64 P rows + 64 Q rows)
#define WBUF_HALVES (128 * WS16)                    // 5120
#define EDGE_DYN    ((SF_HALVES + PQ_HALVES + 2 * WBUF_HALVES) * 2)    // 60416 B
#define NPMID_HALVES (128 * MIDS16)
#define NP_DYN      ((NPMID_HALVES + 2 * NPMID_HALVES) * 2)            // 104448 B

// ---------------- device globals (allocation-free scratch) ----------------
__device__ __half g_w1ab[2 * 2 * 128 * 128];  // [side][which(a/b)][n][k] fp16
__device__ __half g_wsh[2 * 128 * 32];        // [side][n][k=32]: k<16 a-rows, k16 radial
__device__ __half g_w2h[2 * 128 * 128];       // [side][n][k] fp16 (W2^T)
__device__ __half g_Ph[2 * NNODES * 128];     // h@W1a per side (fp16)
__device__ __half g_Qh[2 * NNODES * 128];     // h@W1b + b1 per side (fp16)
__device__ float  g_hagg[NNODES * H];
__device__ float  g_xagg[NNODES * 3];

__device__ __forceinline__ float siluf(float x) { return x / (1.0f + __expf(-x)); }
__device__ __forceinline__ float sigf(float x)  { return 1.0f / (1.0f + __expf(-x)); }

__device__ __forceinline__ uint32_t smem_u32(const void* p) {
    uint32_t a;
    asm("{ .reg .u64 t; cvta.to.shared.u64 t, %1; cvt.u32.u64 %0, t; }" : "=r"(a) : "l"(p));
    return a;
}
__device__ __forceinline__ void cp16(uint32_t daddr, const void* g) {
    asm volatile("cp.async.cg.shared.global [%0], [%1], 16;" :: "r"(daddr), "l"(g));
}
#define CP_COMMIT() asm volatile("cp.async.commit_group;" ::: "memory")
#define CP_WAIT2()  asm volatile("cp.async.wait_group 2;" ::: "memory")
#define CP_WAIT1()  asm volatile("cp.async.wait_group 1;" ::: "memory")
#define CP_WAIT0()  asm volatile("cp.async.wait_group 0;" ::: "memory")

__device__ __forceinline__ void red_v4(float* addr, float a, float b, float c, float d) {
    asm volatile("red.global.add.v4.f32 [%0], {%1, %2, %3, %4};"
                 :: "l"(addr), "f"(a), "f"(b), "f"(c), "f"(d) : "memory");
}

__device__ __forceinline__ void mma_f16(float d[4], const uint32_t a[4], const uint32_t b[2]) {
    asm volatile(
        "mma.sync.aligned.m16n8k16.row.col.f32.f16.f16.f32 "
        "{%0,%1,%2,%3},{%4,%5,%6,%7},{%8,%9},{%0,%1,%2,%3};"
        : "+f"(d[0]), "+f"(d[1]), "+f"(d[2]), "+f"(d[3])
        : "r"(a[0]), "r"(a[1]), "r"(a[2]), "r"(a[3]), "r"(b[0]), "r"(b[1]));
}

// ---------------- prep: build fp16 transposed weight layouts ----------------
__global__ void prep_kernel(const float* __restrict__ wc1, const float* __restrict__ we1,
                            const float* __restrict__ wc2, const float* __restrict__ we2) {
    int i = blockIdx.x * blockDim.x + threadIdx.x;
    if (i < 2 * 2 * 128 * 128) {
        int side  = i >> 15;
        int rem   = i & 32767;
        int which = rem >> 14;
        int nk    = rem & 16383;
        int n = nk >> 7, k = nk & 127;
        const float* w = side ? we1 : wc1;
        g_w1ab[i] = __float2half_rn(w[(which * 128 + k) * H + n]);
    }
    if (i < 2 * 128 * 32) {
        int side = i >> 12;
        int rem  = i & 4095;
        int n = rem >> 5, k = rem & 31;
        const float* w = side ? we1 : wc1;
        float v = 0.0f;
        if (k < 16)       v = w[(257 + k) * H + n];
        else if (k == 16) v = w[256 * H + n];
        g_wsh[i] = __float2half_rn(v);
    }
    if (i < 2 * 128 * 128) {
        int side = i >> 14;
        int rem  = i & 16383;
        int n = rem >> 7, k = rem & 127;
        const float* w = side ? we2 : wc2;
        g_w2h[i] = __float2half_rn(w[k * H + n]);
    }
}

__global__ void zero_kernel() {
    const int stride = gridDim.x * blockDim.x;
    int idx = blockIdx.x * blockDim.x + threadIdx.x;
    for (int i = idx; i < NNODES * H; i += stride) g_hagg[i] = 0.0f;
    for (int i = idx; i < NNODES * 3; i += stride) g_xagg[i] = 0.0f;
}

// ---------------- node precompute: P = h@W1a, Q = h@W1b + b1 (fp16 out) ----------------
__global__ __launch_bounds__(THREADS, 2)
void nodeP_kernel(const float* __restrict__ h,
                  const float* __restrict__ bc1, const float* __restrict__ be1) {
    extern __shared__ __half sm[];
    __half* hT = sm;                   // [128][MIDS16]
    __half* wT = sm + NPMID_HALVES;    // [2][128][MIDS16]

    const int tid  = threadIdx.x;
    const int wid  = tid >> 5;
    const int lane = tid & 31;
    const int g    = lane >> 2;
    const int tig  = lane & 3;
    const int side = blockIdx.y;
    const int mBase = (wid >> 1) * 32;
    const int nBase = (wid & 1) * 64;
    const int n0 = blockIdx.x * 128;

    {
        const uint32_t wbase = smem_u32(wT);
        #pragma unroll
        for (int it = 0; it < 16; it++) {
            int idx = tid + it * THREADS;
            int which = idx >> 11;
            int r = (idx >> 4) & 127;
            int q = idx & 15;
            const __half* src = g_w1ab + (((long)side * 2 + which) * 128 + r) * 128 + q * 8;
            uint32_t dst = wbase + (uint32_t)(which * NPMID_HALVES + r * MIDS16 + q * 8) * 2u;
            cp16(dst, src);
        }
        CP_COMMIT();
    }
    {
        const int rb = wid * 16;
        for (int r = rb; r < rb + 16; r++) {
            const int node = n0 + r;
            __half2 p0, p1;
            if (node < NNODES) {
                float4 v = reinterpret_cast<const float4*>(h + (long)node * H)[lane];
                p0 = __floats2half2_rn(v.x, v.y);
                p1 = __floats2half2_rn(v.z, v.w);
            } else {
                p0 = __floats2half2_rn(0.f, 0.f);
                p1 = p0;
            }
            *reinterpret_cast<__half2*>(hT + r * MIDS16 + lane * 4)     = p0;
            *reinterpret_cast<__half2*>(hT + r * MIDS16 + lane * 4 + 2) = p1;
        }
    }
    CP_WAIT0();
    __syncthreads();

    const float* b1 = side ? be1 : bc1;
    const uint32_t* Aw = reinterpret_cast<const uint32_t*>(hT);

    for (int which = 0; which < 2; which++) {
        float acc[2][8][4];
        #pragma unroll
        for (int mf = 0; mf < 2; mf++)
            #pragma unroll
            for (int nf = 0; nf < 8; nf++)
                #pragma unroll
                for (int q = 0; q < 4; q++) acc[mf][nf][q] = 0.0f;

        const uint32_t* ww = reinterpret_cast<const uint32_t*>(wT) + which * (NPMID_HALVES / 2);
        #pragma unroll
        for (int chunk = 0; chunk < 4; chunk++) {
            #pragma unroll
            for (int ks = 0; ks < 2; ks++) {
                const int kw = chunk * 16 + ks * 8;
                uint32_t A[2][4];
                #pragma unroll
                for (int mf = 0; mf < 2; mf++) {
                    const uint32_t* fr  = Aw + (mBase + mf * 16 + g) * (MIDS16 / 2);
                    const uint32_t* fr8 = fr + 8 * (MIDS16 / 2);
                    A[mf][0] = fr [kw + tig];
                    A[mf][1] = fr8[kw + tig];
                    A[mf][2] = fr [kw + tig + 4];
                    A[mf][3] = fr8[kw + tig + 4];
                }
                uint32_t B[8][2];
                #pragma unroll
                for (int nf = 0; nf < 8; nf++) {
                    const uint32_t* br = ww + (nBase + nf * 8 + g) * (MIDS16 / 2);
                    B[nf][0] = br[kw + tig];
                    B[nf][1] = br[kw + tig + 4];
                }
                #pragma unroll
                for (int mf = 0; mf < 2; mf++)
                    #pragma unroll
                    for (int nf = 0; nf < 8; nf++)
                        mma_f16(acc[mf][nf], A[mf], B[nf]);
            }
        }

        __half* out = (which ? g_Qh : g_Ph) + (long)side * NNODES * 128;
        #pragma unroll
        for (int mf = 0; mf < 2; mf++) {
            const int r0 = mBase + mf * 16 + g, r1 = r0 + 8;
            const int node0 = n0 + r0, node1 = n0 + r1;
            #pragma unroll
            for (int nf = 0; nf < 8; nf++) {
                const int c0 = nBase + nf * 8 + 2 * tig;
                const float bb0 = which ? b1[c0]     : 0.0f;
                const float bb1 = which ? b1[c0 + 1] : 0.0f;
                if (node0 < NNODES)
                    *reinterpret_cast<__half2*>(out + (long)node0 * 128 + c0) =
                        __floats2half2_rn(acc[mf][nf][0] + bb0, acc[mf][nf][1] + bb1);
                if (node1 < NNODES)
                    *reinterpret_cast<__half2*>(out + (long)node1 * 128 + c0) =
                        __floats2half2_rn(acc[mf][nf][2] + bb0, acc[mf][nf][3] + bb1);
            }
        }
    }
}

// stage one weight chunk into w buffer `buf`: k==-1 -> wsh, else w2h chunk k
__device__ __forceinline__ void prefetch_w(int k, int buf, uint32_t w_base,
                                           int tid, int side) {
    #pragma unroll
    for (int j = 0; j < 4; j++) {
        const int idx = tid + j * THREADS_E;   // 0..511
        const int r = idx >> 2;
        const int q = idx & 3;
        const __half* srcp = (k < 0)
            ? g_wsh + (long)side * 128 * 32 + (long)r * 32 + q * 8
            : g_w2h + (long)side * 128 * 128 + (long)r * 128 + k * 32 + q * 8;
        const uint32_t dst = w_base +
            (uint32_t)(buf * WBUF_HALVES + r * WS16 + q * 8) * 2u;
        cp16(dst, srcp);
    }
}

// --------------- edge kernel: 64 edges, 128 threads, PQ cp.async staging ---------------
__global__ __launch_bounds__(THREADS_E, 4)
void edge_kernel(const float* __restrict__ coords,
                 const float* __restrict__ a, const int* __restrict__ src,
                 const int* __restrict__ dst,
                 const float* __restrict__ bc2, const float* __restrict__ wc3,
                 const float* __restrict__ be2,
                 const float* __restrict__ wa,  const float* __restrict__ ba)
{
    extern __shared__ __half smem_h[];
    __half* sF  = smem_h;                            // [64][SF16]
    __half* pq  = smem_h + SF_HALVES;                // [128][PQS16]: rows 0-63 P, 64-127 Q
    __half* mid = pq;                                // mid aliases P rows (overwritten in place)
    __half* w_h = smem_h + SF_HALVES + PQ_HALVES;    // [2 bufs][128][WS16]

    __shared__ float diffs_s[TILE_M][3];
    __shared__ float rad_s[TILE_M];
    __shared__ float head_s[TILE_M];
    __shared__ int   src_s[TILE_M], dst_s[TILE_M];

    const int tid   = threadIdx.x;
    const int lane  = tid & 31;
    const int wid   = tid >> 5;
    const int g     = lane >> 2;
    const int tig   = lane & 3;
    const int side  = blockIdx.y;
    const int mBase = (wid >> 1) * 32;
    const int nBase = (wid & 1) * 64;
    const long e0   = (long)blockIdx.x * TILE_M;

    const uint32_t w_base  = smem_u32(w_h);
    const uint32_t pq_base = smem_u32(pq);

    prefetch_w(-1, 0, w_base, tid, side); CP_COMMIT();   // G1: wsh
    prefetch_w(0,  1, w_base, tid, side); CP_COMMIT();   // G2: w2[0]

    // ---- prologue part 1: indices + geometry (parallel) ----
    if (tid < TILE_M) {
        const int e = tid;
        const int s = src[e0 + e], d = dst[e0 + e];
        src_s[e] = s; dst_s[e] = d;
        head_s[e] = side ? ba[0] : 0.0f;
        const float dx = coords[(long)s * 3 + 0] - coords[(long)d * 3 + 0];
        const float dy = coords[(long)s * 3 + 1] - coords[(long)d * 3 + 1];
        const float dz = coords[(long)s * 3 + 2] - coords[(long)d * 3 + 2];
        diffs_s[e][0] = dx; diffs_s[e][1] = dy; diffs_s[e][2] = dz;
        const float r = dx * dx + dy * dy + dz * dz;
        rad_s[e] = r;
        sF[e * SF16 + 16] = __float2half_rn(r);
    }
    __syncthreads();   // src_s/dst_s visible for PQ staging

    // ---- stage P[src] / Q[dst] rows (fp16, 256B each) via cp.async: G3 ----
    {
        const __half* Pg = g_Ph + (long)side * NNODES * 128;
        const __half* Qg = g_Qh + (long)side * NNODES * 128;
        #pragma unroll
        for (int j = 0; j < 16; j++) {
            const int idx = tid + j * THREADS_E;   // 0..2047
            const int row = idx >> 4;              // 0..127
            const int q   = idx & 15;
            const __half* srcp = (row < 64)
                ? Pg + (long)src_s[row] * 128 + q * 8
                : Qg + (long)dst_s[row - 64] * 128 + q * 8;
            cp16(pq_base + (uint32_t)(row * PQS16 + q * 8) * 2u, srcp);
        }
        CP_COMMIT();
    }

    // ---- prologue part 2: a tile + zero pad ----
    {
        const int e = tid >> 1, hh = tid & 1;
        const float4 v0 = *reinterpret_cast<const float4*>(a + (e0 + e) * FE + hh * 8);
        const float4 v1 = *reinterpret_cast<const float4*>(a + (e0 + e) * FE + hh * 8 + 4);
        __half* row = sF + e * SF16 + hh * 8;
        *reinterpret_cast<__half2*>(row)     = __floats2half2_rn(v0.x, v0.y);
        *reinterpret_cast<__half2*>(row + 2) = __floats2half2_rn(v0.z, v0.w);
        *reinterpret_cast<__half2*>(row + 4) = __floats2half2_rn(v1.x, v1.y);
        *reinterpret_cast<__half2*>(row + 6) = __floats2half2_rn(v1.z, v1.w);
        const __half z = __float2half_rn(0.0f);
        if (hh == 0) { for (int k = 17; k < 24; k++) sF[e * SF16 + k] = z; }
        else         { for (int k = 24; k < 32; k++) sF[e * SF16 + k] = z; }
    }

    float acc[2][8][4];
    #pragma unroll
    for (int mf = 0; mf < 2; mf++)
        #pragma unroll
        for (int nf = 0; nf < 8; nf++)
            #pragma unroll
            for (int q = 0; q < 4; q++) acc[mf][nf][q] = 0.0f;

    // ============ mainloop: chunk0 = small K=32 GEMM, chunks 1-4 = layer 2 ============
    for (int c = 0; c < NCHUNKS; c++) {
        if (c == 0) { CP_WAIT2(); } else { CP_WAIT1(); }
        __syncthreads();

        if (c == NCHUNK1) {
            // ---- layer-1 assembly: acc(small) + P + Q -> silu -> mid (in-place on P) ----
            #pragma unroll
            for (int mf = 0; mf < 2; mf++) {
                const int r0 = mBase + mf * 16 + g, r1 = r0 + 8;
                const __half* P0 = pq + r0 * PQS16;
                const __half* P1 = pq + r1 * PQS16;
                const __half* Q0 = pq + (64 + r0) * PQS16;
                const __half* Q1 = pq + (64 + r1) * PQS16;
                #pragma unroll
                for (int nf = 0; nf < 8; nf++) {
                    const int c0 = nBase + nf * 8 + 2 * tig;
                    const float2 pa = __half22float2(*reinterpret_cast<const __half2*>(P0 + c0));
                    const float2 qa = __half22float2(*reinterpret_cast<const __half2*>(Q0 + c0));
                    const float2 pb = __half22float2(*reinterpret_cast<const __half2*>(P1 + c0));
                    const float2 qb = __half22float2(*reinterpret_cast<const __half2*>(Q1 + c0));
                    *reinterpret_cast<__half2*>(const_cast<__half*>(P0) + c0) = __floats2half2_rn(
                        siluf(acc[mf][nf][0] + pa.x + qa.x),
                        siluf(acc[mf][nf][1] + pa.y + qa.y));
                    *reinterpret_cast<__half2*>(const_cast<__half*>(P1) + c0) = __floats2half2_rn(
                        siluf(acc[mf][nf][2] + pb.x + qb.x),
                        siluf(acc[mf][nf][3] + pb.y + qb.y));
                    #pragma unroll
                    for (int q = 0; q < 4; q++) acc[mf][nf][q] = 0.0f;
                }
            }
            __syncthreads();   // mid visible cross-warp before layer-2 A reads
        }

        const uint32_t* ww = reinterpret_cast<const uint32_t*>(w_h) +
                             ((c & 1) * WBUF_HALVES) / 2;
        const uint32_t* Aw;
        int awstr, kwbase;
        if (c == 0) { Aw = reinterpret_cast<const uint32_t*>(sF);  awstr = SF16 / 2;  kwbase = 0; }
        else        { Aw = reinterpret_cast<const uint32_t*>(mid); awstr = PQS16 / 2; kwbase = (c - 1) * 16; }

        #pragma unroll
        for (int ks = 0; ks < 2; ks++) {
            const int kw  = kwbase + ks * 8;
            const int bw  = ks * 8 + tig;
            uint32_t A[2][4];
            #pragma unroll
            for (int mf = 0; mf < 2; mf++) {
                const uint32_t* fr  = Aw + (mBase + mf * 16 + g) * awstr;
                const uint32_t* fr8 = fr + 8 * awstr;
                const int akw = (c == 0) ? ks * 8 : kw;
                A[mf][0] = fr [akw + tig];
                A[mf][1] = fr8[akw + tig];
                A[mf][2] = fr [akw + tig + 4];
                A[mf][3] = fr8[akw + tig + 4];
            }
            uint32_t B[8][2];
            #pragma unroll
            for (int nf = 0; nf < 8; nf++) {
                const uint32_t* br = ww + (nBase + nf * 8 + g) * (WS16 / 2);
                B[nf][0] = br[bw];
                B[nf][1] = br[bw + 4];
            }
            #pragma unroll
            for (int mf = 0; mf < 2; mf++)
                #pragma unroll
                for (int nf = 0; nf < 8; nf++)
                    mma_f16(acc[mf][nf], A[mf], B[nf]);
        }

        __syncthreads();   // buf (c&1) reads done -> safe to refill
        if (c + 1 <= 3 && c + 2 < NCHUNKS) prefetch_w(c + 1, c & 1, w_base, tid, side);
        CP_COMMIT();
    }

    // ---- layer-2 epilogue: bias + silu ----
    {
        const float* b2 = side ? be2 : bc2;
        #pragma unroll
        for (int mf = 0; mf < 2; mf++)
            #pragma unroll
            for (int nf = 0; nf < 8; nf++) {
                const int c0 = nBase + nf * 8 + 2 * tig;
                acc[mf][nf][0] = siluf(acc[mf][nf][0] + b2[c0]);
                acc[mf][nf][1] = siluf(acc[mf][nf][1] + b2[c0 + 1]);
                acc[mf][nf][2] = siluf(acc[mf][nf][2] + b2[c0]);
                acc[mf][nf][3] = siluf(acc[mf][nf][3] + b2[c0 + 1]);
            }
    }

    // ---- head: scale (side 0) or att_pre (side 1) ----
    {
        const float* hw = side ? wa : wc3;
        #pragma unroll
        for (int mf = 0; mf < 2; mf++) {
            float p0 = 0.0f, p1 = 0.0f;
            #pragma unroll
            for (int nf = 0; nf < 8; nf++) {
                const int c0 = nBase + nf * 8 + 2 * tig;
                const float w0 = hw[c0], w1 = hw[c0 + 1];
                p0 += acc[mf][nf][0] * w0 + acc[mf][nf][1] * w1;
                p1 += acc[mf][nf][2] * w0 + acc[mf][nf][3] * w1;
            }
            p0 += __shfl_xor_sync(0xffffffffu, p0, 1);
            p0 += __shfl_xor_sync(0xffffffffu, p0, 2);
            p1 += __shfl_xor_sync(0xffffffffu, p1, 1);
            p1 += __shfl_xor_sync(0xffffffffu, p1, 2);
            if (tig == 0) {
                const int r0 = mBase + mf * 16 + g;
                atomicAdd(&head_s[r0], p0);
                atomicAdd(&head_s[r0 + 8], p1);
            }
        }
    }
    __syncthreads();

    if (side) {
        const bool odd = (tig & 1);
        #pragma unroll
        for (int mf = 0; mf < 2; mf++) {
            const int r0 = mBase + mf * 16 + g, r1 = r0 + 8;
            const long d0 = (long)dst_s[r0] * H, d1 = (long)dst_s[r1] * H;
            const float s0 = sigf(head_s[r0]), s1 = sigf(head_s[r1]);
            #pragma unroll
            for (int nf = 0; nf < 8; nf++) {
                const float v0 = s0 * acc[mf][nf][0];
                const float v1 = s0 * acc[mf][nf][1];
                const float v2 = s1 * acc[mf][nf][2];
                const float v3 = s1 * acc[mf][nf][3];
                const float t0 = odd ? v0 : v2;
                const float t1 = odd ? v1 : v3;
                const float rx = __shfl_xor_sync(0xffffffffu, t0, 1);
                const float ry = __shfl_xor_sync(0xffffffffu, t1, 1);
                if (!odd) {
                    red_v4(&g_hagg[d0 + nBase + nf * 8 + 2 * tig], v0, v1, rx, ry);
                } else {
                    red_v4(&g_hagg[d1 + nBase + nf * 8 + 2 * (tig - 1)], rx, ry, v2, v3);
                }
            }
        }
    } else if (tid < TILE_M) {
        const int e = tid;
        const float sc = head_s[e] / (rad_s[e] + 1.0f);
        const long db = (long)dst_s[e] * 3;
        atomicAdd(&g_xagg[db + 0], sc * diffs_s[e][0]);
        atomicAdd(&g_xagg[db + 1], sc * diffs_s[e][1]);
        atomicAdd(&g_xagg[db + 2], sc * diffs_s[e][2]);
    }
}

// --------------------------- node kernel (TILE_N=32) ---------------------------
__global__ __launch_bounds__(128)
void node_kernel(const float* __restrict__ h, const float* __restrict__ coords,
                 const float* __restrict__ wn1, const float* __restrict__ bn1,
                 const float* __restrict__ wn2, const float* __restrict__ bn2,
                 float* __restrict__ out_h, float* __restrict__ out_x)
{
    __shared__ __align__(16) float hh_s[TILE_N][H];
    __shared__ __align__(16) float ha_s[TILE_N][H];
    __shared__ __align__(16) float n_s[TILE_N][H];

    const int tid  = threadIdx.x;
    const int warp = tid >> 5;
    const int lane = tid & 31;
    const int n0   = blockIdx.x * TILE_N;

    for (int e = warp; e < TILE_N; e += 4) {
        int node = n0 + e;
        if (node >= NNODES) node = NNODES - 1;
        #pragma unroll
        for (int k = lane; k < H; k += 32) {
            hh_s[e][k] = h[(long)node * H + k];
            ha_s[e][k] = g_hagg[(long)node * H + k];
        }
    }
    __syncthreads();

    const int j = tid;
    float acc[TILE_N];
    {
        const float b1 = bn1[j];
        #pragma unroll
        for (int e = 0; e < TILE_N; e++) acc[e] = b1;
        for (int k = 0; k < H; k += 4) {
            const float wA0 = wn1[(k+0)*H + j], wA1 = wn1[(k+1)*H + j];
            const float wA2 = wn1[(k+2)*H + j], wA3 = wn1[(k+3)*H + j];
            const float wB0 = wn1[(H+k+0)*H + j], wB1 = wn1[(H+k+1)*H + j];
            const float wB2 = wn1[(H+k+2)*H + j], wB3 = wn1[(H+k+3)*H + j];
            #pragma unroll
            for (int e = 0; e < TILE_N; e++) {
                const float4 hv = *reinterpret_cast<const float4*>(&hh_s[e][k]);
                const float4 av = *reinterpret_cast<const float4*>(&ha_s[e][k]);
                float s = acc[e];
                s = fmaf(hv.x, wA0, s); s = fmaf(hv.y, wA1, s);
                s = fmaf(hv.z, wA2, s); s = fmaf(hv.w, wA3, s);
                s = fmaf(av.x, wB0, s); s = fmaf(av.y, wB1, s);
                s = fmaf(av.z, wB2, s); s = fmaf(av.w, wB3, s);
                acc[e] = s;
            }
        }
        #pragma unroll
        for (int e = 0; e < TILE_N; e++) n_s[e][j] = siluf(acc[e]);
    }
    __syncthreads();

    {
        const float b2 = bn2[j];
        #pragma unroll
        for (int e = 0; e < TILE_N; e++) acc[e] = b2;
        for (int k = 0; k < H; k += 4) {
            const float w0 = wn2[(k+0)*H + j], w1 = wn2[(k+1)*H + j];
            const float w2 = wn2[(k+2)*H + j], w3 = wn2[(k+3)*H + j];
            #pragma unroll
            for (int e = 0; e < TILE_N; e++) {
                const float4 nv = *reinterpret_cast<const float4*>(&n_s[e][k]);
                float s = acc[e];
                s = fmaf(nv.x, w0, s); s = fmaf(nv.y, w1, s);
                s = fmaf(nv.z, w2, s); s = fmaf(nv.w, w3, s);
                acc[e] = s;
            }
        }
        #pragma unroll
        for (int e = 0; e < TILE_N; e++) {
            const int node = n0 + e;
            if (node < NNODES)
                out_h[(long)node * H + j] = h[(long)node * H + j] + acc[e];
        }
    }

    if (tid < TILE_N * 3) {
        const int e = tid / 3, c = tid % 3;
        const int node = n0 + e;
        if (node < NNODES)
            out_x[(long)node * 3 + c] = coords[(long)node * 3 + c] + g_xagg[(long)node * 3 + c];
    }
}

extern "C" void kernel_launch(void* const* d_in, const int* in_sizes, int n_in,
                              void* d_out, int out_size) {
    const float* h      = (const float*)d_in[0];
    const float* coords = (const float*)d_in[1];
    const float* a      = (const float*)d_in[2];
    const int*   src    = (const int*)  d_in[3];
    const int*   dst    = (const int*)  d_in[4];
    const float* wc1 = (const float*)d_in[5];
    const float* bc1 = (const float*)d_in[6];
    const float* wc2 = (const float*)d_in[7];
    const float* bc2 = (const float*)d_in[8];
    const float* wc3 = (const float*)d_in[9];
    const float* we1 = (const float*)d_in[10];
    const float* be1 = (const float*)d_in[11];
    const float* we2 = (const float*)d_in[12];
    const float* be2 = (const float*)d_in[13];
    const float* wa  = (const float*)d_in[14];
    const float* ba  = (const float*)d_in[15];
    const float* wn1 = (const float*)d_in[16];
    const float* bn1 = (const float*)d_in[17];
    const float* wn2 = (const float*)d_in[18];
    const float* bn2 = (const float*)d_in[19];

    float* out_h = (float*)d_out;
    float* out_x = out_h + (long)NNODES * H;

    static bool attr_set = false;
    if (!attr_set) {
        cudaFuncSetAttribute(edge_kernel,
                             cudaFuncAttributeMaxDynamicSharedMemorySize, EDGE_DYN);
        cudaFuncSetAttribute(nodeP_kernel,
                             cudaFuncAttributeMaxDynamicSharedMemorySize, NP_DYN);
        attr_set = true;
    }

    prep_kernel<<<256, 256>>>(wc1, we1, wc2, we2);
    zero_kernel<<<1024, 256>>>();
    dim3 pgrid((NNODES + 127) / 128, 2);
    nodeP_kernel<<<pgrid, THREADS, NP_DYN>>>(h, bc1, be1);
    dim3 egrid(NEDGES / TILE_M, 2);
    edge_kernel<<<egrid, THREADS_E, EDGE_DYN>>>(coords, a, src, dst,
                                                bc2, wc3, be2, wa, ba);
    node_kernel<<<(NNODES + TILE_N - 1) / TILE_N, 128>>>(h, coords, wn1, bn1, wn2, bn2,
                                                         out_h, out_x);
}

// round 12
// speedup vs baseline: 1.0634x; 1.0634x over previous
#include <cuda_runtime.h>
#include <cuda_fp16.h>
#include <cstdint>

#define NNODES 50000
#define NEDGES 800000
#define H 128
#define FE 16
#define TILE_M 64
#define THREADS_E 128
#define THREADS 256
#define TILE_N 32
#define NCHUNKS 5
#define NCHUNK1 1

// fp16 strides (halves)
#define MIDS16 136     // 68 words, 68%32=4 -> conflict-free
#define SF16   40      // 20 words -> conflict-free
#define WS16   40

#define MID_HALVES  (TILE_M * MIDS16)               // 8704
#define SF_HALVES   (TILE_M * SF16)                 // 2560
#define WBUF_HALVES (128 * WS16)                    // 5120
#define EDGE_DYN    ((MID_HALVES + SF_HALVES + 2 * WBUF_HALVES) * 2)   // 43008 B
#define NPMID_HALVES (128 * MIDS16)
#define NP_DYN      ((NPMID_HALVES + 2 * NPMID_HALVES) * 2)            // 104448 B

// ---------------- device globals (allocation-free scratch) ----------------
__device__ __half g_w1ab[2 * 2 * 128 * 128];  // [side][which(a/b)][n][k] fp16
__device__ __half g_wsh[2 * 128 * 32];        // [side][n][k=32]: k<16 a-rows, k16 radial
__device__ __half g_w2h[2 * 128 * 128];       // [side][n][k] fp16 (W2^T)
__device__ __half g_Ph[2 * NNODES * 128];     // h@W1a per side (fp16)
__device__ __half g_Qh[2 * NNODES * 128];     // h@W1b + b1 per side (fp16)
__device__ float  g_hagg[NNODES * H];
__device__ float  g_xagg[NNODES * 3];

__device__ __forceinline__ float siluf(float x) { return x / (1.0f + __expf(-x)); }
__device__ __forceinline__ float sigf(float x)  { return 1.0f / (1.0f + __expf(-x)); }

__device__ __forceinline__ uint32_t smem_u32(const void* p) {
    uint32_t a;
    asm("{ .reg .u64 t; cvta.to.shared.u64 t, %1; cvt.u32.u64 %0, t; }" : "=r"(a) : "l"(p));
    return a;
}
__device__ __forceinline__ void cp16(uint32_t daddr, const void* g) {
    asm volatile("cp.async.cg.shared.global [%0], [%1], 16;" :: "r"(daddr), "l"(g));
}
#define CP_COMMIT() asm volatile("cp.async.commit_group;" ::: "memory")
#define CP_WAIT1()  asm volatile("cp.async.wait_group 1;" ::: "memory")
#define CP_WAIT0()  asm volatile("cp.async.wait_group 0;" ::: "memory")

__device__ __forceinline__ void red_v4(float* addr, float a, float b, float c, float d) {
    asm volatile("red.global.add.v4.f32 [%0], {%1, %2, %3, %4};"
                 :: "l"(addr), "f"(a), "f"(b), "f"(c), "f"(d) : "memory");
}

__device__ __forceinline__ void mma_f16(float d[4], const uint32_t a[4], const uint32_t b[2]) {
    asm volatile(
        "mma.sync.aligned.m16n8k16.row.col.f32.f16.f16.f32 "
        "{%0,%1,%2,%3},{%4,%5,%6,%7},{%8,%9},{%0,%1,%2,%3};"
        : "+f"(d[0]), "+f"(d[1]), "+f"(d[2]), "+f"(d[3])
        : "r"(a[0]), "r"(a[1]), "r"(a[2]), "r"(a[3]), "r"(b[0]), "r"(b[1]));
}

// ---------------- prep: build fp16 transposed weight layouts ----------------
__global__ void prep_kernel(const float* __restrict__ wc1, const float* __restrict__ we1,
                            const float* __restrict__ wc2, const float* __restrict__ we2) {
    int i = blockIdx.x * blockDim.x + threadIdx.x;
    if (i < 2 * 2 * 128 * 128) {
        int side  = i >> 15;
        int rem   = i & 32767;
        int which = rem >> 14;
        int nk    = rem & 16383;
        int n = nk >> 7, k = nk & 127;
        const float* w = side ? we1 : wc1;
        g_w1ab[i] = __float2half_rn(w[(which * 128 + k) * H + n]);
    }
    if (i < 2 * 128 * 32) {
        int side = i >> 12;
        int rem  = i & 4095;
        int n = rem >> 5, k = rem & 31;
        const float* w = side ? we1 : wc1;
        float v = 0.0f;
        if (k < 16)       v = w[(257 + k) * H + n];
        else if (k == 16) v = w[256 * H + n];
        g_wsh[i] = __float2half_rn(v);
    }
    if (i < 2 * 128 * 128) {
        int side = i >> 14;
        int rem  = i & 16383;
        int n = rem >> 7, k = rem & 127;
        const float* w = side ? we2 : wc2;
        g_w2h[i] = __float2half_rn(w[k * H + n]);
    }
}

__global__ void zero_kernel() {
    const int stride = gridDim.x * blockDim.x;
    int idx = blockIdx.x * blockDim.x + threadIdx.x;
    for (int i = idx; i < NNODES * H; i += stride) g_hagg[i] = 0.0f;
    for (int i = idx; i < NNODES * 3; i += stride) g_xagg[i] = 0.0f;
}

// ---------------- node precompute: P = h@W1a, Q = h@W1b + b1 (fp16 out) ----------------
__global__ __launch_bounds__(THREADS, 2)
void nodeP_kernel(const float* __restrict__ h,
                  const float* __restrict__ bc1, const float* __restrict__ be1) {
    extern __shared__ __half sm[];
    __half* hT = sm;                   // [128][MIDS16]
    __half* wT = sm + NPMID_HALVES;    // [2][128][MIDS16]

    const int tid  = threadIdx.x;
    const int wid  = tid >> 5;
    const int lane = tid & 31;
    const int g    = lane >> 2;
    const int tig  = lane & 3;
    const int side = blockIdx.y;
    const int mBase = (wid >> 1) * 32;
    const int nBase = (wid & 1) * 64;
    const int n0 = blockIdx.x * 128;

    {
        const uint32_t wbase = smem_u32(wT);
        #pragma unroll
        for (int it = 0; it < 16; it++) {
            int idx = tid + it * THREADS;
            int which = idx >> 11;
            int r = (idx >> 4) & 127;
            int q = idx & 15;
            const __half* src = g_w1ab + (((long)side * 2 + which) * 128 + r) * 128 + q * 8;
            uint32_t dst = wbase + (uint32_t)(which * NPMID_HALVES + r * MIDS16 + q * 8) * 2u;
            cp16(dst, src);
        }
        CP_COMMIT();
    }
    {
        const int rb = wid * 16;
        for (int r = rb; r < rb + 16; r++) {
            const int node = n0 + r;
            __half2 p0, p1;
            if (node < NNODES) {
                float4 v = reinterpret_cast<const float4*>(h + (long)node * H)[lane];
                p0 = __floats2half2_rn(v.x, v.y);
                p1 = __floats2half2_rn(v.z, v.w);
            } else {
                p0 = __floats2half2_rn(0.f, 0.f);
                p1 = p0;
            }
            *reinterpret_cast<__half2*>(hT + r * MIDS16 + lane * 4)     = p0;
            *reinterpret_cast<__half2*>(hT + r * MIDS16 + lane * 4 + 2) = p1;
        }
    }
    CP_WAIT0();
    __syncthreads();

    const float* b1 = side ? be1 : bc1;
    const uint32_t* Aw = reinterpret_cast<const uint32_t*>(hT);

    for (int which = 0; which < 2; which++) {
        float acc[2][8][4];
        #pragma unroll
        for (int mf = 0; mf < 2; mf++)
            #pragma unroll
            for (int nf = 0; nf < 8; nf++)
                #pragma unroll
                for (int q = 0; q < 4; q++) acc[mf][nf][q] = 0.0f;

        const uint32_t* ww = reinterpret_cast<const uint32_t*>(wT) + which * (NPMID_HALVES / 2);
        #pragma unroll
        for (int chunk = 0; chunk < 4; chunk++) {
            #pragma unroll
            for (int ks = 0; ks < 2; ks++) {
                const int kw = chunk * 16 + ks * 8;
                uint32_t A[2][4];
                #pragma unroll
                for (int mf = 0; mf < 2; mf++) {
                    const uint32_t* fr  = Aw + (mBase + mf * 16 + g) * (MIDS16 / 2);
                    const uint32_t* fr8 = fr + 8 * (MIDS16 / 2);
                    A[mf][0] = fr [kw + tig];
                    A[mf][1] = fr8[kw + tig];
                    A[mf][2] = fr [kw + tig + 4];
                    A[mf][3] = fr8[kw + tig + 4];
                }
                uint32_t B[8][2];
                #pragma unroll
                for (int nf = 0; nf < 8; nf++) {
                    const uint32_t* br = ww + (nBase + nf * 8 + g) * (MIDS16 / 2);
                    B[nf][0] = br[kw + tig];
                    B[nf][1] = br[kw + tig + 4];
                }
                #pragma unroll
                for (int mf = 0; mf < 2; mf++)
                    #pragma unroll
                    for (int nf = 0; nf < 8; nf++)
                        mma_f16(acc[mf][nf], A[mf], B[nf]);
            }
        }

        __half* out = (which ? g_Qh : g_Ph) + (long)side * NNODES * 128;
        #pragma unroll
        for (int mf = 0; mf < 2; mf++) {
            const int r0 = mBase + mf * 16 + g, r1 = r0 + 8;
            const int node0 = n0 + r0, node1 = n0 + r1;
            #pragma unroll
            for (int nf = 0; nf < 8; nf++) {
                const int c0 = nBase + nf * 8 + 2 * tig;
                const float bb0 = which ? b1[c0]     : 0.0f;
                const float bb1 = which ? b1[c0 + 1] : 0.0f;
                if (node0 < NNODES)
                    *reinterpret_cast<__half2*>(out + (long)node0 * 128 + c0) =
                        __floats2half2_rn(acc[mf][nf][0] + bb0, acc[mf][nf][1] + bb1);
                if (node1 < NNODES)
                    *reinterpret_cast<__half2*>(out + (long)node1 * 128 + c0) =
                        __floats2half2_rn(acc[mf][nf][2] + bb0, acc[mf][nf][3] + bb1);
            }
        }
    }
}

// stage one K=32 chunk (this side) into w buffer `buf` -- 128 threads
__device__ __forceinline__ void prefetch_chunk(int c, int buf, uint32_t w_base,
                                               int tid, int side) {
    #pragma unroll
    for (int j = 0; j < 4; j++) {
        const int idx = tid + j * THREADS_E;   // 0..511
        const int r = idx >> 2;
        const int q = idx & 3;
        const __half* srcp = (c == 0)
            ? g_wsh + (long)side * 128 * 32 + (long)r * 32 + q * 8
            : g_w2h + (long)side * 128 * 128 + (long)r * 128 + (c - 1) * 32 + q * 8;
        const uint32_t dst = w_base +
            (uint32_t)(buf * WBUF_HALVES + r * WS16 + q * 8) * 2u;
        cp16(dst, srcp);
    }
}

// --------- edge kernel: 64 edges, 128 threads, 4 CTAs/SM, fp16 PQ gather ---------
__global__ __launch_bounds__(THREADS_E, 4)
void edge_kernel(const float* __restrict__ coords,
                 const float* __restrict__ a, const int* __restrict__ src,
                 const int* __restrict__ dst,
                 const float* __restrict__ bc2, const float* __restrict__ wc3,
                 const float* __restrict__ be2,
                 const float* __restrict__ wa,  const float* __restrict__ ba)
{
    extern __shared__ __half smem_h[];
    __half* mid = smem_h;                        // [64][MIDS16]
    __half* sF  = smem_h + MID_HALVES;           // [64][SF16]
    __half* w_h = smem_h + MID_HALVES + SF_HALVES;  // [2 bufs][128][WS16]

    __shared__ float diffs_s[TILE_M][3];
    __shared__ float rad_s[TILE_M];
    __shared__ float head_s[TILE_M];
    __shared__ int   src_s[TILE_M], dst_s[TILE_M];

    const int tid   = threadIdx.x;
    const int wid   = tid >> 5;            // 0..3
    const int lane  = tid & 31;
    const int g     = lane >> 2;
    const int tig   = lane & 3;
    const int side  = blockIdx.y;
    const int mBase = (wid >> 1) * 32;
    const int nBase = (wid & 1) * 64;
    const long e0   = (long)blockIdx.x * TILE_M;

    const uint32_t w_base = smem_u32(w_h);

    prefetch_chunk(0, 0, w_base, tid, side); CP_COMMIT();
    prefetch_chunk(1, 1, w_base, tid, side); CP_COMMIT();

    // ---- fully parallel prologue ----
    if (tid < TILE_M) {
        const int e = tid;
        const int s = src[e0 + e], d = dst[e0 + e];
        src_s[e] = s; dst_s[e] = d;
        head_s[e] = side ? ba[0] : 0.0f;
        const float dx = coords[(long)s * 3 + 0] - coords[(long)d * 3 + 0];
        const float dy = coords[(long)s * 3 + 1] - coords[(long)d * 3 + 1];
        const float dz = coords[(long)s * 3 + 2] - coords[(long)d * 3 + 2];
        diffs_s[e][0] = dx; diffs_s[e][1] = dy; diffs_s[e][2] = dz;
        const float r = dx * dx + dy * dy + dz * dz;
        rad_s[e] = r;
        sF[e * SF16 + 16] = __float2half_rn(r);
    }
    {
        const int e = tid >> 1, hh = tid & 1;
        const float4 v0 = *reinterpret_cast<const float4*>(a + (e0 + e) * FE + hh * 8);
        const float4 v1 = *reinterpret_cast<const float4*>(a + (e0 + e) * FE + hh * 8 + 4);
        __half* row = sF + e * SF16 + hh * 8;
        *reinterpret_cast<__half2*>(row)     = __floats2half2_rn(v0.x, v0.y);
        *reinterpret_cast<__half2*>(row + 2) = __floats2half2_rn(v0.z, v0.w);
        *reinterpret_cast<__half2*>(row + 4) = __floats2half2_rn(v1.x, v1.y);
        *reinterpret_cast<__half2*>(row + 6) = __floats2half2_rn(v1.z, v1.w);
        const __half z = __float2half_rn(0.0f);
        if (hh == 0) { for (int k = 17; k < 24; k++) sF[e * SF16 + k] = z; }
        else         { for (int k = 24; k < 32; k++) sF[e * SF16 + k] = z; }
    }
    __syncthreads();

    float acc[2][8][4];
    #pragma unroll
    for (int mf = 0; mf < 2; mf++)
        #pragma unroll
        for (int nf = 0; nf < 8; nf++)
            #pragma unroll
            for (int q = 0; q < 4; q++) acc[mf][nf][q] = 0.0f;

    // ============ mainloop: chunk0 = small K=32 GEMM, chunks 1-4 = layer 2 ============
    for (int c = 0; c < NCHUNKS; c++) {
        if (c == NCHUNK1) {
            // ---- layer-1 assembly: acc(small) + P[src] + Q[dst] (fp16 gather) -> silu -> mid ----
            const __half* Pp = g_Ph + (long)side * NNODES * 128;
            const __half* Qp = g_Qh + (long)side * NNODES * 128;
            #pragma unroll
            for (int mf = 0; mf < 2; mf++) {
                const int r0 = mBase + mf * 16 + g, r1 = r0 + 8;
                const __half* p0 = Pp + (long)src_s[r0] * 128;
                const __half* q0 = Qp + (long)dst_s[r0] * 128;
                const __half* p1 = Pp + (long)src_s[r1] * 128;
                const __half* q1 = Qp + (long)dst_s[r1] * 128;
                __half* m0 = mid + r0 * MIDS16;
                __half* m1 = mid + r1 * MIDS16;
                #pragma unroll
                for (int nf = 0; nf < 8; nf++) {
                    const int c0 = nBase + nf * 8 + 2 * tig;
                    const float2 pa = __half22float2(*reinterpret_cast<const __half2*>(p0 + c0));
                    const float2 qa = __half22float2(*reinterpret_cast<const __half2*>(q0 + c0));
                    const float2 pb = __half22float2(*reinterpret_cast<const __half2*>(p1 + c0));
                    const float2 qb = __half22float2(*reinterpret_cast<const __half2*>(q1 + c0));
                    *reinterpret_cast<__half2*>(m0 + c0) = __floats2half2_rn(
                        siluf(acc[mf][nf][0] + pa.x + qa.x),
                        siluf(acc[mf][nf][1] + pa.y + qa.y));
                    *reinterpret_cast<__half2*>(m1 + c0) = __floats2half2_rn(
                        siluf(acc[mf][nf][2] + pb.x + qb.x),
                        siluf(acc[mf][nf][3] + pb.y + qb.y));
                    #pragma unroll
                    for (int q = 0; q < 4; q++) acc[mf][nf][q] = 0.0f;
                }
            }
        }

        CP_WAIT1();
        __syncthreads();

        const uint32_t* ww = reinterpret_cast<const uint32_t*>(w_h) +
                             ((c & 1) * WBUF_HALVES) / 2;
        const uint32_t* Aw;
        int awstr, kwbase;
        if (c == 0) { Aw = reinterpret_cast<const uint32_t*>(sF);  awstr = SF16 / 2;   kwbase = 0; }
        else        { Aw = reinterpret_cast<const uint32_t*>(mid); awstr = MIDS16 / 2; kwbase = (c - 1) * 16; }

        #pragma unroll
        for (int ks = 0; ks < 2; ks++) {
            const int kw  = kwbase + ks * 8;
            const int bw  = ks * 8 + tig;
            uint32_t A[2][4];
            #pragma unroll
            for (int mf = 0; mf < 2; mf++) {
                const uint32_t* fr  = Aw + (mBase + mf * 16 + g) * awstr;
                const uint32_t* fr8 = fr + 8 * awstr;
                const int akw = (c == 0) ? ks * 8 : kw;
                A[mf][0] = fr [akw + tig];
                A[mf][1] = fr8[akw + tig];
                A[mf][2] = fr [akw + tig + 4];
                A[mf][3] = fr8[akw + tig + 4];
            }
            uint32_t B[8][2];
            #pragma unroll
            for (int nf = 0; nf < 8; nf++) {
                const uint32_t* br = ww + (nBase + nf * 8 + g) * (WS16 / 2);
                B[nf][0] = br[bw];
                B[nf][1] = br[bw + 4];
            }
            #pragma unroll
            for (int mf = 0; mf < 2; mf++)
                #pragma unroll
                for (int nf = 0; nf < 8; nf++)
                    mma_f16(acc[mf][nf], A[mf], B[nf]);
        }

        __syncthreads();
        if (c + 2 < NCHUNKS) prefetch_chunk(c + 2, c & 1, w_base, tid, side);
        CP_COMMIT();
    }

    // ---- layer-2 epilogue: bias + silu ----
    {
        const float* b2 = side ? be2 : bc2;
        #pragma unroll
        for (int mf = 0; mf < 2; mf++)
            #pragma unroll
            for (int nf = 0; nf < 8; nf++) {
                const int c0 = nBase + nf * 8 + 2 * tig;
                acc[mf][nf][0] = siluf(acc[mf][nf][0] + b2[c0]);
                acc[mf][nf][1] = siluf(acc[mf][nf][1] + b2[c0 + 1]);
                acc[mf][nf][2] = siluf(acc[mf][nf][2] + b2[c0]);
                acc[mf][nf][3] = siluf(acc[mf][nf][3] + b2[c0 + 1]);
            }
    }

    // ---- head: scale (side 0) or att_pre (side 1) ----
    {
        const float* hw = side ? wa : wc3;
        #pragma unroll
        for (int mf = 0; mf < 2; mf++) {
            float p0 = 0.0f, p1 = 0.0f;
            #pragma unroll
            for (int nf = 0; nf < 8; nf++) {
                const int c0 = nBase + nf * 8 + 2 * tig;
                const float w0 = hw[c0], w1 = hw[c0 + 1];
                p0 += acc[mf][nf][0] * w0 + acc[mf][nf][1] * w1;
                p1 += acc[mf][nf][2] * w0 + acc[mf][nf][3] * w1;
            }
            p0 += __shfl_xor_sync(0xffffffffu, p0, 1);
            p0 += __shfl_xor_sync(0xffffffffu, p0, 2);
            p1 += __shfl_xor_sync(0xffffffffu, p1, 1);
            p1 += __shfl_xor_sync(0xffffffffu, p1, 2);
            if (tig == 0) {
                const int r0 = mBase + mf * 16 + g;
                atomicAdd(&head_s[r0], p0);
                atomicAdd(&head_s[r0 + 8], p1);
            }
        }
    }
    __syncthreads();

    if (side) {
        const bool odd = (tig & 1);
        #pragma unroll
        for (int mf = 0; mf < 2; mf++) {
            const int r0 = mBase + mf * 16 + g, r1 = r0 + 8;
            const long d0 = (long)dst_s[r0] * H, d1 = (long)dst_s[r1] * H;
            const float s0 = sigf(head_s[r0]), s1 = sigf(head_s[r1]);
            #pragma unroll
            for (int nf = 0; nf < 8; nf++) {
                const float v0 = s0 * acc[mf][nf][0];
                const float v1 = s0 * acc[mf][nf][1];
                const float v2 = s1 * acc[mf][nf][2];
                const float v3 = s1 * acc[mf][nf][3];
                const float t0 = odd ? v0 : v2;
                const float t1 = odd ? v1 : v3;
                const float rx = __shfl_xor_sync(0xffffffffu, t0, 1);
                const float ry = __shfl_xor_sync(0xffffffffu, t1, 1);
                if (!odd) {
                    red_v4(&g_hagg[d0 + nBase + nf * 8 + 2 * tig], v0, v1, rx, ry);
                } else {
                    red_v4(&g_hagg[d1 + nBase + nf * 8 + 2 * (tig - 1)], rx, ry, v2, v3);
                }
            }
        }
    } else if (tid < TILE_M) {
        const int e = tid;
        const float sc = head_s[e] / (rad_s[e] + 1.0f);
        const long db = (long)dst_s[e] * 3;
        atomicAdd(&g_xagg[db + 0], sc * diffs_s[e][0]);
        atomicAdd(&g_xagg[db + 1], sc * diffs_s[e][1]);
        atomicAdd(&g_xagg[db + 2], sc * diffs_s[e][2]);
    }
}

// --------------------------- node kernel (TILE_N=32) ---------------------------
__global__ __launch_bounds__(128)
void node_kernel(const float* __restrict__ h, const float* __restrict__ coords,
                 const float* __restrict__ wn1, const float* __restrict__ bn1,
                 const float* __restrict__ wn2, const float* __restrict__ bn2,
                 float* __restrict__ out_h, float* __restrict__ out_x)
{
    __shared__ __align__(16) float hh_s[TILE_N][H];
    __shared__ __align__(16) float ha_s[TILE_N][H];
    __shared__ __align__(16) float n_s[TILE_N][H];

    const int tid  = threadIdx.x;
    const int warp = tid >> 5;
    const int lane = tid & 31;
    const int n0   = blockIdx.x * TILE_N;

    for (int e = warp; e < TILE_N; e += 4) {
        int node = n0 + e;
        if (node >= NNODES) node = NNODES - 1;
        #pragma unroll
        for (int k = lane; k < H; k += 32) {
            hh_s[e][k] = h[(long)node * H + k];
            ha_s[e][k] = g_hagg[(long)node * H + k];
        }
    }
    __syncthreads();

    const int j = tid;
    float acc[TILE_N];
    {
        const float b1 = bn1[j];
        #pragma unroll
        for (int e = 0; e < TILE_N; e++) acc[e] = b1;
        for (int k = 0; k < H; k += 4) {
            const float wA0 = wn1[(k+0)*H + j], wA1 = wn1[(k+1)*H + j];
            const float wA2 = wn1[(k+2)*H + j], wA3 = wn1[(k+3)*H + j];
            const float wB0 = wn1[(H+k+0)*H + j], wB1 = wn1[(H+k+1)*H + j];
            const float wB2 = wn1[(H+k+2)*H + j], wB3 = wn1[(H+k+3)*H + j];
            #pragma unroll
            for (int e = 0; e < TILE_N; e++) {
                const float4 hv = *reinterpret_cast<const float4*>(&hh_s[e][k]);
                const float4 av = *reinterpret_cast<const float4*>(&ha_s[e][k]);
                float s = acc[e];
                s = fmaf(hv.x, wA0, s); s = fmaf(hv.y, wA1, s);
                s = fmaf(hv.z, wA2, s); s = fmaf(hv.w, wA3, s);
                s = fmaf(av.x, wB0, s); s = fmaf(av.y, wB1, s);
                s = fmaf(av.z, wB2, s); s = fmaf(av.w, wB3, s);
                acc[e] = s;
            }
        }
        #pragma unroll
        for (int e = 0; e < TILE_N; e++) n_s[e][j] = siluf(acc[e]);
    }
    __syncthreads();

    {
        const float b2 = bn2[j];
        #pragma unroll
        for (int e = 0; e < TILE_N; e++) acc[e] = b2;
        for (int k = 0; k < H; k += 4) {
            const float w0 = wn2[(k+0)*H + j], w1 = wn2[(k+1)*H + j];
            const float w2 = wn2[(k+2)*H + j], w3 = wn2[(k+3)*H + j];
            #pragma unroll
            for (int e = 0; e < TILE_N; e++) {
                const float4 nv = *reinterpret_cast<const float4*>(&n_s[e][k]);
                float s = acc[e];
                s = fmaf(nv.x, w0, s); s = fmaf(nv.y, w1, s);
                s = fmaf(nv.z, w2, s); s = fmaf(nv.w, w3, s);
                acc[e] = s;
            }
        }
        #pragma unroll
        for (int e = 0; e < TILE_N; e++) {
            const int node = n0 + e;
            if (node < NNODES)
                out_h[(long)node * H + j] = h[(long)node * H + j] + acc[e];
        }
    }

    if (tid < TILE_N * 3) {
        const int e = tid / 3, c = tid % 3;
        const int node = n0 + e;
        if (node < NNODES)
            out_x[(long)node * 3 + c] = coords[(long)node * 3 + c] + g_xagg[(long)node * 3 + c];
    }
}

extern "C" void kernel_launch(void* const* d_in, const int* in_sizes, int n_in,
                              void* d_out, int out_size) {
    const float* h      = (const float*)d_in[0];
    const float* coords = (const float*)d_in[1];
    const float* a      = (const float*)d_in[2];
    const int*   src    = (const int*)  d_in[3];
    const int*   dst    = (const int*)  d_in[4];
    const float* wc1 = (const float*)d_in[5];
    const float* bc1 = (const float*)d_in[6];
    const float* wc2 = (const float*)d_in[7];
    const float* bc2 = (const float*)d_in[8];
    const float* wc3 = (const float*)d_in[9];
    const float* we1 = (const float*)d_in[10];
    const float* be1 = (const float*)d_in[11];
    const float* we2 = (const float*)d_in[12];
    const float* be2 = (const float*)d_in[13];
    const float* wa  = (const float*)d_in[14];
    const float* ba  = (const float*)d_in[15];
    const float* wn1 = (const float*)d_in[16];
    const float* bn1 = (const float*)d_in[17];
    const float* wn2 = (const float*)d_in[18];
    const float* bn2 = (const float*)d_in[19];

    float* out_h = (float*)d_out;
    float* out_x = out_h + (long)NNODES * H;

    static bool attr_set = false;
    if (!attr_set) {
        cudaFuncSetAttribute(edge_kernel,
                             cudaFuncAttributeMaxDynamicSharedMemorySize, EDGE_DYN);
        cudaFuncSetAttribute(nodeP_kernel,
                             cudaFuncAttributeMaxDynamicSharedMemorySize, NP_DYN);
        attr_set = true;
    }

    prep_kernel<<<256, 256>>>(wc1, we1, wc2, we2);
    zero_kernel<<<1024, 256>>>();
    dim3 pgrid((NNODES + 127) / 128, 2);
    nodeP_kernel<<<pgrid, THREADS, NP_DYN>>>(h, bc1, be1);
    dim3 egrid(NEDGES / TILE_M, 2);
    edge_kernel<<<egrid, THREADS_E, EDGE_DYN>>>(coords, a, src, dst,
                                                bc2, wc3, be2, wa, ba);
    node_kernel<<<(NNODES + TILE_N - 1) / TILE_N, 128>>>(h, coords, wn1, bn1, wn2, bn2,
                                                         out_h, out_x);
}

// round 13
// speedup vs baseline: 1.2188x; 1.1461x over previous
#include <cuda_runtime.h>
#include <cuda_fp16.h>
#include <cstdint>

#define NNODES 50000
#define NEDGES 800000
#define H 128
#define FE 16
#define TILE_M 64
#define THREADS_E 128
#define THREADS 256
#define NCHUNKS 5
#define NCHUNK1 1

// fp16 strides (halves)
#define MIDS16 136     // 68 words, 68%32=4 -> conflict-free
#define SF16   40      // 20 words -> conflict-free
#define WS16   40

#define MID_HALVES  (TILE_M * MIDS16)               // 8704
#define SF_HALVES   (TILE_M * SF16)                 // 2560
#define WBUF_HALVES (128 * WS16)                    // 5120
#define EDGE_DYN    ((MID_HALVES + SF_HALVES + 2 * WBUF_HALVES) * 2)   // 43008 B
#define NPMID_HALVES (128 * MIDS16)
#define NP_DYN      ((NPMID_HALVES + 2 * NPMID_HALVES) * 2)            // 104448 B

// node-MLP kernel tiles
#define TILE_NM 64
#define NS16 264           // 132 words, 132%32=4 -> conflict-free
#define NA_HALVES (TILE_NM * NS16)                  // 16896
#define NODE_DYN  ((NA_HALVES + 2 * WBUF_HALVES) * 2)   // 54272 B
#define NCHUNKS_N 12
#define NCHUNK1_N 8

// ---------------- device globals (allocation-free scratch) ----------------
__device__ __half g_w1ab[2 * 2 * 128 * 128];  // [side][which(a/b)][n][k] fp16
__device__ __half g_wsh[2 * 128 * 32];        // [side][n][k=32]
__device__ __half g_w2h[2 * 128 * 128];       // [side][n][k] fp16 (W2^T)
__device__ __half g_wn1t[128 * 256];          // [n][k] fp16 (Wn1^T)
__device__ __half g_wn2t[128 * 128];          // [n][k] fp16 (Wn2^T)
__device__ __half g_Ph[2 * NNODES * 128];     // h@W1a per side (fp16)
__device__ __half g_Qh[2 * NNODES * 128];     // h@W1b + b1 per side (fp16)
__device__ float  g_hagg[NNODES * H];
__device__ float  g_xagg[NNODES * 3];

__device__ __forceinline__ float siluf(float x) { return x / (1.0f + __expf(-x)); }
__device__ __forceinline__ float sigf(float x)  { return 1.0f / (1.0f + __expf(-x)); }

__device__ __forceinline__ uint32_t smem_u32(const void* p) {
    uint32_t a;
    asm("{ .reg .u64 t; cvta.to.shared.u64 t, %1; cvt.u32.u64 %0, t; }" : "=r"(a) : "l"(p));
    return a;
}
__device__ __forceinline__ void cp16(uint32_t daddr, const void* g) {
    asm volatile("cp.async.cg.shared.global [%0], [%1], 16;" :: "r"(daddr), "l"(g));
}
#define CP_COMMIT() asm volatile("cp.async.commit_group;" ::: "memory")
#define CP_WAIT1()  asm volatile("cp.async.wait_group 1;" ::: "memory")
#define CP_WAIT0()  asm volatile("cp.async.wait_group 0;" ::: "memory")

__device__ __forceinline__ void red_v4(float* addr, float a, float b, float c, float d) {
    asm volatile("red.global.add.v4.f32 [%0], {%1, %2, %3, %4};"
                 :: "l"(addr), "f"(a), "f"(b), "f"(c), "f"(d) : "memory");
}

__device__ __forceinline__ void mma_f16(float d[4], const uint32_t a[4], const uint32_t b[2]) {
    asm volatile(
        "mma.sync.aligned.m16n8k16.row.col.f32.f16.f16.f32 "
        "{%0,%1,%2,%3},{%4,%5,%6,%7},{%8,%9},{%0,%1,%2,%3};"
        : "+f"(d[0]), "+f"(d[1]), "+f"(d[2]), "+f"(d[3])
        : "r"(a[0]), "r"(a[1]), "r"(a[2]), "r"(a[3]), "r"(b[0]), "r"(b[1]));
}

// ---------------- prep: build fp16 transposed weight layouts ----------------
__global__ void prep_kernel(const float* __restrict__ wc1, const float* __restrict__ we1,
                            const float* __restrict__ wc2, const float* __restrict__ we2,
                            const float* __restrict__ wn1, const float* __restrict__ wn2) {
    int i = blockIdx.x * blockDim.x + threadIdx.x;
    if (i < 2 * 2 * 128 * 128) {
        int side  = i >> 15;
        int rem   = i & 32767;
        int which = rem >> 14;
        int nk    = rem & 16383;
        int n = nk >> 7, k = nk & 127;
        const float* w = side ? we1 : wc1;
        g_w1ab[i] = __float2half_rn(w[(which * 128 + k) * H + n]);
    }
    if (i < 2 * 128 * 32) {
        int side = i >> 12;
        int rem  = i & 4095;
        int n = rem >> 5, k = rem & 31;
        const float* w = side ? we1 : wc1;
        float v = 0.0f;
        if (k < 16)       v = w[(257 + k) * H + n];
        else if (k == 16) v = w[256 * H + n];
        g_wsh[i] = __float2half_rn(v);
    }
    if (i < 2 * 128 * 128) {
        int side = i >> 14;
        int rem  = i & 16383;
        int n = rem >> 7, k = rem & 127;
        const float* w = side ? we2 : wc2;
        g_w2h[i] = __float2half_rn(w[k * H + n]);
    }
    if (i < 128 * 256) {
        int n = i >> 8, k = i & 255;
        g_wn1t[i] = __float2half_rn(wn1[k * H + n]);
    }
    if (i < 128 * 128) {
        int n = i >> 7, k = i & 127;
        g_wn2t[i] = __float2half_rn(wn2[k * H + n]);
    }
}

__global__ void zero_kernel() {
    const int stride = gridDim.x * blockDim.x;
    int idx = blockIdx.x * blockDim.x + threadIdx.x;
    for (int i = idx; i < NNODES * H; i += stride) g_hagg[i] = 0.0f;
    for (int i = idx; i < NNODES * 3; i += stride) g_xagg[i] = 0.0f;
}

// ---------------- node precompute: P = h@W1a, Q = h@W1b + b1 (fp16 out) ----------------
__global__ __launch_bounds__(THREADS, 2)
void nodeP_kernel(const float* __restrict__ h,
                  const float* __restrict__ bc1, const float* __restrict__ be1) {
    extern __shared__ __half sm[];
    __half* hT = sm;                   // [128][MIDS16]
    __half* wT = sm + NPMID_HALVES;    // [2][128][MIDS16]

    const int tid  = threadIdx.x;
    const int wid  = tid >> 5;
    const int lane = tid & 31;
    const int g    = lane >> 2;
    const int tig  = lane & 3;
    const int side = blockIdx.y;
    const int mBase = (wid >> 1) * 32;
    const int nBase = (wid & 1) * 64;
    const int n0 = blockIdx.x * 128;

    {
        const uint32_t wbase = smem_u32(wT);
        #pragma unroll
        for (int it = 0; it < 16; it++) {
            int idx = tid + it * THREADS;
            int which = idx >> 11;
            int r = (idx >> 4) & 127;
            int q = idx & 15;
            const __half* src = g_w1ab + (((long)side * 2 + which) * 128 + r) * 128 + q * 8;
            uint32_t dst = wbase + (uint32_t)(which * NPMID_HALVES + r * MIDS16 + q * 8) * 2u;
            cp16(dst, src);
        }
        CP_COMMIT();
    }
    {
        const int rb = wid * 16;
        for (int r = rb; r < rb + 16; r++) {
            const int node = n0 + r;
            __half2 p0, p1;
            if (node < NNODES) {
                float4 v = reinterpret_cast<const float4*>(h + (long)node * H)[lane];
                p0 = __floats2half2_rn(v.x, v.y);
                p1 = __floats2half2_rn(v.z, v.w);
            } else {
                p0 = __floats2half2_rn(0.f, 0.f);
                p1 = p0;
            }
            *reinterpret_cast<__half2*>(hT + r * MIDS16 + lane * 4)     = p0;
            *reinterpret_cast<__half2*>(hT + r * MIDS16 + lane * 4 + 2) = p1;
        }
    }
    CP_WAIT0();
    __syncthreads();

    const float* b1 = side ? be1 : bc1;
    const uint32_t* Aw = reinterpret_cast<const uint32_t*>(hT);

    for (int which = 0; which < 2; which++) {
        float acc[2][8][4];
        #pragma unroll
        for (int mf = 0; mf < 2; mf++)
            #pragma unroll
            for (int nf = 0; nf < 8; nf++)
                #pragma unroll
                for (int q = 0; q < 4; q++) acc[mf][nf][q] = 0.0f;

        const uint32_t* ww = reinterpret_cast<const uint32_t*>(wT) + which * (NPMID_HALVES / 2);
        #pragma unroll
        for (int chunk = 0; chunk < 4; chunk++) {
            #pragma unroll
            for (int ks = 0; ks < 2; ks++) {
                const int kw = chunk * 16 + ks * 8;
                uint32_t A[2][4];
                #pragma unroll
                for (int mf = 0; mf < 2; mf++) {
                    const uint32_t* fr  = Aw + (mBase + mf * 16 + g) * (MIDS16 / 2);
                    const uint32_t* fr8 = fr + 8 * (MIDS16 / 2);
                    A[mf][0] = fr [kw + tig];
                    A[mf][1] = fr8[kw + tig];
                    A[mf][2] = fr [kw + tig + 4];
                    A[mf][3] = fr8[kw + tig + 4];
                }
                uint32_t B[8][2];
                #pragma unroll
                for (int nf = 0; nf < 8; nf++) {
                    const uint32_t* br = ww + (nBase + nf * 8 + g) * (MIDS16 / 2);
                    B[nf][0] = br[kw + tig];
                    B[nf][1] = br[kw + tig + 4];
                }
                #pragma unroll
                for (int mf = 0; mf < 2; mf++)
                    #pragma unroll
                    for (int nf = 0; nf < 8; nf++)
                        mma_f16(acc[mf][nf], A[mf], B[nf]);
            }
        }

        __half* out = (which ? g_Qh : g_Ph) + (long)side * NNODES * 128;
        #pragma unroll
        for (int mf = 0; mf < 2; mf++) {
            const int r0 = mBase + mf * 16 + g, r1 = r0 + 8;
            const int node0 = n0 + r0, node1 = n0 + r1;
            #pragma unroll
            for (int nf = 0; nf < 8; nf++) {
                const int c0 = nBase + nf * 8 + 2 * tig;
                const float bb0 = which ? b1[c0]     : 0.0f;
                const float bb1 = which ? b1[c0 + 1] : 0.0f;
                if (node0 < NNODES)
                    *reinterpret_cast<__half2*>(out + (long)node0 * 128 + c0) =
                        __floats2half2_rn(acc[mf][nf][0] + bb0, acc[mf][nf][1] + bb1);
                if (node1 < NNODES)
                    *reinterpret_cast<__half2*>(out + (long)node1 * 128 + c0) =
                        __floats2half2_rn(acc[mf][nf][2] + bb0, acc[mf][nf][3] + bb1);
            }
        }
    }
}

// stage one K=32 chunk (edge weights) into w buffer `buf` -- 128 threads
__device__ __forceinline__ void prefetch_chunk(int c, int buf, uint32_t w_base,
                                               int tid, int side) {
    #pragma unroll
    for (int j = 0; j < 4; j++) {
        const int idx = tid + j * THREADS_E;
        const int r = idx >> 2;
        const int q = idx & 3;
        const __half* srcp = (c == 0)
            ? g_wsh + (long)side * 128 * 32 + (long)r * 32 + q * 8
            : g_w2h + (long)side * 128 * 128 + (long)r * 128 + (c - 1) * 32 + q * 8;
        const uint32_t dst = w_base +
            (uint32_t)(buf * WBUF_HALVES + r * WS16 + q * 8) * 2u;
        cp16(dst, srcp);
    }
}

// --------- edge kernel: 64 edges, 128 threads, 4 CTAs/SM, fp16 PQ gather ---------
__global__ __launch_bounds__(THREADS_E, 4)
void edge_kernel(const float* __restrict__ coords,
                 const float* __restrict__ a, const int* __restrict__ src,
                 const int* __restrict__ dst,
                 const float* __restrict__ bc2, const float* __restrict__ wc3,
                 const float* __restrict__ be2,
                 const float* __restrict__ wa,  const float* __restrict__ ba)
{
    extern __shared__ __half smem_h[];
    __half* mid = smem_h;                        // [64][MIDS16]
    __half* sF  = smem_h + MID_HALVES;           // [64][SF16]
    __half* w_h = smem_h + MID_HALVES + SF_HALVES;  // [2 bufs][128][WS16]

    __shared__ float diffs_s[TILE_M][3];
    __shared__ float rad_s[TILE_M];
    __shared__ float head_s[TILE_M];
    __shared__ int   src_s[TILE_M], dst_s[TILE_M];

    const int tid   = threadIdx.x;
    const int wid   = tid >> 5;
    const int lane  = tid & 31;
    const int g     = lane >> 2;
    const int tig   = lane & 3;
    const int side  = blockIdx.y;
    const int mBase = (wid >> 1) * 32;
    const int nBase = (wid & 1) * 64;
    const long e0   = (long)blockIdx.x * TILE_M;

    const uint32_t w_base = smem_u32(w_h);

    prefetch_chunk(0, 0, w_base, tid, side); CP_COMMIT();
    prefetch_chunk(1, 1, w_base, tid, side); CP_COMMIT();

    if (tid < TILE_M) {
        const int e = tid;
        const int s = src[e0 + e], d = dst[e0 + e];
        src_s[e] = s; dst_s[e] = d;
        head_s[e] = side ? ba[0] : 0.0f;
        const float dx = coords[(long)s * 3 + 0] - coords[(long)d * 3 + 0];
        const float dy = coords[(long)s * 3 + 1] - coords[(long)d * 3 + 1];
        const float dz = coords[(long)s * 3 + 2] - coords[(long)d * 3 + 2];
        diffs_s[e][0] = dx; diffs_s[e][1] = dy; diffs_s[e][2] = dz;
        const float r = dx * dx + dy * dy + dz * dz;
        rad_s[e] = r;
        sF[e * SF16 + 16] = __float2half_rn(r);
    }
    {
        const int e = tid >> 1, hh = tid & 1;
        const float4 v0 = *reinterpret_cast<const float4*>(a + (e0 + e) * FE + hh * 8);
        const float4 v1 = *reinterpret_cast<const float4*>(a + (e0 + e) * FE + hh * 8 + 4);
        __half* row = sF + e * SF16 + hh * 8;
        *reinterpret_cast<__half2*>(row)     = __floats2half2_rn(v0.x, v0.y);
        *reinterpret_cast<__half2*>(row + 2) = __floats2half2_rn(v0.z, v0.w);
        *reinterpret_cast<__half2*>(row + 4) = __floats2half2_rn(v1.x, v1.y);
        *reinterpret_cast<__half2*>(row + 6) = __floats2half2_rn(v1.z, v1.w);
        const __half z = __float2half_rn(0.0f);
        if (hh == 0) { for (int k = 17; k < 24; k++) sF[e * SF16 + k] = z; }
        else         { for (int k = 24; k < 32; k++) sF[e * SF16 + k] = z; }
    }
    __syncthreads();

    float acc[2][8][4];
    #pragma unroll
    for (int mf = 0; mf < 2; mf++)
        #pragma unroll
        for (int nf = 0; nf < 8; nf++)
            #pragma unroll
            for (int q = 0; q < 4; q++) acc[mf][nf][q] = 0.0f;

    for (int c = 0; c < NCHUNKS; c++) {
        if (c == NCHUNK1) {
            const __half* Pp = g_Ph + (long)side * NNODES * 128;
            const __half* Qp = g_Qh + (long)side * NNODES * 128;
            #pragma unroll
            for (int mf = 0; mf < 2; mf++) {
                const int r0 = mBase + mf * 16 + g, r1 = r0 + 8;
                const __half* p0 = Pp + (long)src_s[r0] * 128;
                const __half* q0 = Qp + (long)dst_s[r0] * 128;
                const __half* p1 = Pp + (long)src_s[r1] * 128;
                const __half* q1 = Qp + (long)dst_s[r1] * 128;
                __half* m0 = mid + r0 * MIDS16;
                __half* m1 = mid + r1 * MIDS16;
                #pragma unroll
                for (int nf = 0; nf < 8; nf++) {
                    const int c0 = nBase + nf * 8 + 2 * tig;
                    const float2 pa = __half22float2(*reinterpret_cast<const __half2*>(p0 + c0));
                    const float2 qa = __half22float2(*reinterpret_cast<const __half2*>(q0 + c0));
                    const float2 pb = __half22float2(*reinterpret_cast<const __half2*>(p1 + c0));
                    const float2 qb = __half22float2(*reinterpret_cast<const __half2*>(q1 + c0));
                    *reinterpret_cast<__half2*>(m0 + c0) = __floats2half2_rn(
                        siluf(acc[mf][nf][0] + pa.x + qa.x),
                        siluf(acc[mf][nf][1] + pa.y + qa.y));
                    *reinterpret_cast<__half2*>(m1 + c0) = __floats2half2_rn(
                        siluf(acc[mf][nf][2] + pb.x + qb.x),
                        siluf(acc[mf][nf][3] + pb.y + qb.y));
                    #pragma unroll
                    for (int q = 0; q < 4; q++) acc[mf][nf][q] = 0.0f;
                }
            }
        }

        CP_WAIT1();
        __syncthreads();

        const uint32_t* ww = reinterpret_cast<const uint32_t*>(w_h) +
                             ((c & 1) * WBUF_HALVES) / 2;
        const uint32_t* Aw;
        int awstr, kwbase;
        if (c == 0) { Aw = reinterpret_cast<const uint32_t*>(sF);  awstr = SF16 / 2;   kwbase = 0; }
        else        { Aw = reinterpret_cast<const uint32_t*>(mid); awstr = MIDS16 / 2; kwbase = (c - 1) * 16; }

        #pragma unroll
        for (int ks = 0; ks < 2; ks++) {
            const int kw  = kwbase + ks * 8;
            const int bw  = ks * 8 + tig;
            uint32_t A[2][4];
            #pragma unroll
            for (int mf = 0; mf < 2; mf++) {
                const uint32_t* fr  = Aw + (mBase + mf * 16 + g) * awstr;
                const uint32_t* fr8 = fr + 8 * awstr;
                const int akw = (c == 0) ? ks * 8 : kw;
                A[mf][0] = fr [akw + tig];
                A[mf][1] = fr8[akw + tig];
                A[mf][2] = fr [akw + tig + 4];
                A[mf][3] = fr8[akw + tig + 4];
            }
            uint32_t B[8][2];
            #pragma unroll
            for (int nf = 0; nf < 8; nf++) {
                const uint32_t* br = ww + (nBase + nf * 8 + g) * (WS16 / 2);
                B[nf][0] = br[bw];
                B[nf][1] = br[bw + 4];
            }
            #pragma unroll
            for (int mf = 0; mf < 2; mf++)
                #pragma unroll
                for (int nf = 0; nf < 8; nf++)
                    mma_f16(acc[mf][nf], A[mf], B[nf]);
        }

        __syncthreads();
        if (c + 2 < NCHUNKS) prefetch_chunk(c + 2, c & 1, w_base, tid, side);
        CP_COMMIT();
    }

    {
        const float* b2 = side ? be2 : bc2;
        #pragma unroll
        for (int mf = 0; mf < 2; mf++)
            #pragma unroll
            for (int nf = 0; nf < 8; nf++) {
                const int c0 = nBase + nf * 8 + 2 * tig;
                acc[mf][nf][0] = siluf(acc[mf][nf][0] + b2[c0]);
                acc[mf][nf][1] = siluf(acc[mf][nf][1] + b2[c0 + 1]);
                acc[mf][nf][2] = siluf(acc[mf][nf][2] + b2[c0]);
                acc[mf][nf][3] = siluf(acc[mf][nf][3] + b2[c0 + 1]);
            }
    }

    {
        const float* hw = side ? wa : wc3;
        #pragma unroll
        for (int mf = 0; mf < 2; mf++) {
            float p0 = 0.0f, p1 = 0.0f;
            #pragma unroll
            for (int nf = 0; nf < 8; nf++) {
                const int c0 = nBase + nf * 8 + 2 * tig;
                const float w0 = hw[c0], w1 = hw[c0 + 1];
                p0 += acc[mf][nf][0] * w0 + acc[mf][nf][1] * w1;
                p1 += acc[mf][nf][2] * w0 + acc[mf][nf][3] * w1;
            }
            p0 += __shfl_xor_sync(0xffffffffu, p0, 1);
            p0 += __shfl_xor_sync(0xffffffffu, p0, 2);
            p1 += __shfl_xor_sync(0xffffffffu, p1, 1);
            p1 += __shfl_xor_sync(0xffffffffu, p1, 2);
            if (tig == 0) {
                const int r0 = mBase + mf * 16 + g;
                atomicAdd(&head_s[r0], p0);
                atomicAdd(&head_s[r0 + 8], p1);
            }
        }
    }
    __syncthreads();

    if (side) {
        const bool odd = (tig & 1);
        #pragma unroll
        for (int mf = 0; mf < 2; mf++) {
            const int r0 = mBase + mf * 16 + g, r1 = r0 + 8;
            const long d0 = (long)dst_s[r0] * H, d1 = (long)dst_s[r1] * H;
            const float s0 = sigf(head_s[r0]), s1 = sigf(head_s[r1]);
            #pragma unroll
            for (int nf = 0; nf < 8; nf++) {
                const float v0 = s0 * acc[mf][nf][0];
                const float v1 = s0 * acc[mf][nf][1];
                const float v2 = s1 * acc[mf][nf][2];
                const float v3 = s1 * acc[mf][nf][3];
                const float t0 = odd ? v0 : v2;
                const float t1 = odd ? v1 : v3;
                const float rx = __shfl_xor_sync(0xffffffffu, t0, 1);
                const float ry = __shfl_xor_sync(0xffffffffu, t1, 1);
                if (!odd) {
                    red_v4(&g_hagg[d0 + nBase + nf * 8 + 2 * tig], v0, v1, rx, ry);
                } else {
                    red_v4(&g_hagg[d1 + nBase + nf * 8 + 2 * (tig - 1)], rx, ry, v2, v3);
                }
            }
        }
    } else if (tid < TILE_M) {
        const int e = tid;
        const float sc = head_s[e] / (rad_s[e] + 1.0f);
        const long db = (long)dst_s[e] * 3;
        atomicAdd(&g_xagg[db + 0], sc * diffs_s[e][0]);
        atomicAdd(&g_xagg[db + 1], sc * diffs_s[e][1]);
        atomicAdd(&g_xagg[db + 2], sc * diffs_s[e][2]);
    }
}

// stage one K=32 chunk of node weights into w buffer `buf`
__device__ __forceinline__ void prefetch_wn(int c, int buf, uint32_t w_base, int tid) {
    #pragma unroll
    for (int j = 0; j < 4; j++) {
        const int idx = tid + j * THREADS_E;
        const int r = idx >> 2;
        const int q = idx & 3;
        const __half* srcp = (c < NCHUNK1_N)
            ? g_wn1t + (long)r * 256 + c * 32 + q * 8
            : g_wn2t + (long)r * 128 + (c - NCHUNK1_N) * 32 + q * 8;
        const uint32_t dst = w_base +
            (uint32_t)(buf * WBUF_HALVES + r * WS16 + q * 8) * 2u;
        cp16(dst, srcp);
    }
}

// --------- node MLP kernel (HMMA): 64 nodes, 128 threads, 4 CTAs/SM ---------
__global__ __launch_bounds__(THREADS_E, 4)
void node_mma_kernel(const float* __restrict__ h, const float* __restrict__ coords,
                     const float* __restrict__ bn1, const float* __restrict__ bn2,
                     float* __restrict__ out_h, float* __restrict__ out_x)
{
    extern __shared__ __half smem_h[];
    __half* At  = smem_h;                    // [64][NS16]: cols 0-127 h, 128-255 hagg
    __half* w_h = smem_h + NA_HALVES;        // [2 bufs][128][WS16]

    const int tid   = threadIdx.x;
    const int wid   = tid >> 5;
    const int lane  = tid & 31;
    const int g     = lane >> 2;
    const int tig   = lane & 3;
    const int mBase = (wid >> 1) * 32;
    const int nBase = (wid & 1) * 64;
    const int n0    = blockIdx.x * TILE_NM;

    const uint32_t w_base = smem_u32(w_h);

    prefetch_wn(0, 0, w_base, tid); CP_COMMIT();
    prefetch_wn(1, 1, w_base, tid); CP_COMMIT();

    // load A tile: each warp 16 rows; lane = float4 index within the 128-col half
    {
        const int rb = wid * 16;
        for (int r = rb; r < rb + 16; r++) {
            int node = n0 + r;
            if (node >= NNODES) node = NNODES - 1;
            float4 hv = reinterpret_cast<const float4*>(h + (long)node * H)[lane];
            float4 av = reinterpret_cast<const float4*>(g_hagg + (long)node * H)[lane];
            *reinterpret_cast<__half2*>(At + r * NS16 + lane * 4)           = __floats2half2_rn(hv.x, hv.y);
            *reinterpret_cast<__half2*>(At + r * NS16 + lane * 4 + 2)       = __floats2half2_rn(hv.z, hv.w);
            *reinterpret_cast<__half2*>(At + r * NS16 + 128 + lane * 4)     = __floats2half2_rn(av.x, av.y);
            *reinterpret_cast<__half2*>(At + r * NS16 + 128 + lane * 4 + 2) = __floats2half2_rn(av.z, av.w);
        }
    }
    __syncthreads();

    float acc[2][8][4];
    #pragma unroll
    for (int mf = 0; mf < 2; mf++)
        #pragma unroll
        for (int nf = 0; nf < 8; nf++)
            #pragma unroll
            for (int q = 0; q < 4; q++) acc[mf][nf][q] = 0.0f;

    for (int c = 0; c < NCHUNKS_N; c++) {
        if (c == NCHUNK1_N) {
            // layer-1 epilogue: bias + silu -> fp16 into A cols 0..127 (in place)
            #pragma unroll
            for (int mf = 0; mf < 2; mf++) {
                const int r0 = mBase + mf * 16 + g, r1 = r0 + 8;
                __half* m0 = At + r0 * NS16;
                __half* m1 = At + r1 * NS16;
                #pragma unroll
                for (int nf = 0; nf < 8; nf++) {
                    const int c0 = nBase + nf * 8 + 2 * tig;
                    const float bb0 = bn1[c0], bb1 = bn1[c0 + 1];
                    *reinterpret_cast<__half2*>(m0 + c0) = __floats2half2_rn(
                        siluf(acc[mf][nf][0] + bb0), siluf(acc[mf][nf][1] + bb1));
                    *reinterpret_cast<__half2*>(m1 + c0) = __floats2half2_rn(
                        siluf(acc[mf][nf][2] + bb0), siluf(acc[mf][nf][3] + bb1));
                    #pragma unroll
                    for (int q = 0; q < 4; q++) acc[mf][nf][q] = 0.0f;
                }
            }
        }

        CP_WAIT1();
        __syncthreads();

        const uint32_t* ww = reinterpret_cast<const uint32_t*>(w_h) +
                             ((c & 1) * WBUF_HALVES) / 2;
        const uint32_t* Aw = reinterpret_cast<const uint32_t*>(At);
        const int kwbase = (c < NCHUNK1_N) ? c * 16 : (c - NCHUNK1_N) * 16;

        #pragma unroll
        for (int ks = 0; ks < 2; ks++) {
            const int kw = kwbase + ks * 8;
            const int bw = ks * 8 + tig;
            uint32_t A[2][4];
            #pragma unroll
            for (int mf = 0; mf < 2; mf++) {
                const uint32_t* fr  = Aw + (mBase + mf * 16 + g) * (NS16 / 2);
                const uint32_t* fr8 = fr + 8 * (NS16 / 2);
                A[mf][0] = fr [kw + tig];
                A[mf][1] = fr8[kw + tig];
                A[mf][2] = fr [kw + tig + 4];
                A[mf][3] = fr8[kw + tig + 4];
            }
            uint32_t B[8][2];
            #pragma unroll
            for (int nf = 0; nf < 8; nf++) {
                const uint32_t* br = ww + (nBase + nf * 8 + g) * (WS16 / 2);
                B[nf][0] = br[bw];
                B[nf][1] = br[bw + 4];
            }
            #pragma unroll
            for (int mf = 0; mf < 2; mf++)
                #pragma unroll
                for (int nf = 0; nf < 8; nf++)
                    mma_f16(acc[mf][nf], A[mf], B[nf]);
        }

        __syncthreads();
        if (c + 2 < NCHUNKS_N) prefetch_wn(c + 2, c & 1, w_base, tid);
        CP_COMMIT();
    }

    // final epilogue: out_h = h + (acc + bn2)
    #pragma unroll
    for (int mf = 0; mf < 2; mf++) {
        const int r0 = mBase + mf * 16 + g, r1 = r0 + 8;
        const int node0 = n0 + r0, node1 = n0 + r1;
        #pragma unroll
        for (int nf = 0; nf < 8; nf++) {
            const int c0 = nBase + nf * 8 + 2 * tig;
            const float bb0 = bn2[c0], bb1 = bn2[c0 + 1];
            if (node0 < NNODES) {
                const float2 hv = *reinterpret_cast<const float2*>(h + (long)node0 * H + c0);
                float2 o = make_float2(hv.x + acc[mf][nf][0] + bb0,
                                       hv.y + acc[mf][nf][1] + bb1);
                *reinterpret_cast<float2*>(out_h + (long)node0 * H + c0) = o;
            }
            if (node1 < NNODES) {
                const float2 hv = *reinterpret_cast<const float2*>(h + (long)node1 * H + c0);
                float2 o = make_float2(hv.x + acc[mf][nf][2] + bb0,
                                       hv.y + acc[mf][nf][3] + bb1);
                *reinterpret_cast<float2*>(out_h + (long)node1 * H + c0) = o;
            }
        }
    }

    // coords out
    for (int idx = tid; idx < TILE_NM * 3; idx += THREADS_E) {
        const int e = idx / 3, cc = idx % 3;
        const int node = n0 + e;
        if (node < NNODES)
            out_x[(long)node * 3 + cc] = coords[(long)node * 3 + cc] + g_xagg[(long)node * 3 + cc];
    }
}

extern "C" void kernel_launch(void* const* d_in, const int* in_sizes, int n_in,
                              void* d_out, int out_size) {
    const float* h      = (const float*)d_in[0];
    const float* coords = (const float*)d_in[1];
    const float* a      = (const float*)d_in[2];
    const int*   src    = (const int*)  d_in[3];
    const int*   dst    = (const int*)  d_in[4];
    const float* wc1 = (const float*)d_in[5];
    const float* bc1 = (const float*)d_in[6];
    const float* wc2 = (const float*)d_in[7];
    const float* bc2 = (const float*)d_in[8];
    const float* wc3 = (const float*)d_in[9];
    const float* we1 = (const float*)d_in[10];
    const float* be1 = (const float*)d_in[11];
    const float* we2 = (const float*)d_in[12];
    const float* be2 = (const float*)d_in[13];
    const float* wa  = (const float*)d_in[14];
    const float* ba  = (const float*)d_in[15];
    const float* wn1 = (const float*)d_in[16];
    const float* bn1 = (const float*)d_in[17];
    const float* wn2 = (const float*)d_in[18];
    const float* bn2 = (const float*)d_in[19];

    float* out_h = (float*)d_out;
    float* out_x = out_h + (long)NNODES * H;

    static bool attr_set = false;
    if (!attr_set) {
        cudaFuncSetAttribute(edge_kernel,
                             cudaFuncAttributeMaxDynamicSharedMemorySize, EDGE_DYN);
        cudaFuncSetAttribute(nodeP_kernel,
                             cudaFuncAttributeMaxDynamicSharedMemorySize, NP_DYN);
        cudaFuncSetAttribute(node_mma_kernel,
                             cudaFuncAttributeMaxDynamicSharedMemorySize, NODE_DYN);
        attr_set = true;
    }

    prep_kernel<<<256, 256>>>(wc1, we1, wc2, we2, wn1, wn2);
    zero_kernel<<<1024, 256>>>();
    dim3 pgrid((NNODES + 127) / 128, 2);
    nodeP_kernel<<<pgrid, THREADS, NP_DYN>>>(h, bc1, be1);
    dim3 egrid(NEDGES / TILE_M, 2);
    edge_kernel<<<egrid, THREADS_E, EDGE_DYN>>>(coords, a, src, dst,
                                                bc2, wc3, be2, wa, ba);
    node_mma_kernel<<<(NNODES + TILE_NM - 1) / TILE_NM, THREADS_E, NODE_DYN>>>(
        h, coords, bn1, bn2, out_h, out_x);
}